// round 4
// baseline (speedup 1.0000x reference)
#include <cuda_runtime.h>
#include <math.h>

// Problem constants (fixed shapes from setup_inputs)
#define BB   2
#define DD   128
#define HH   128
#define WW   128
#define IMG_ELEMS (BB*DD*HH*WW*4)    // 16777216
#define VOX       (BB*DD*HH*WW)      // 4194304

// Effective per-axis weights, double-float pairs:
// E[p][c] = sum_j gauss_tap[j] * keys_weight[p-7+j][c]  (zero pad outside [0,128))
__device__ float g_Ehi[128 * 4];
__device__ float g_Elo[128 * 4];

// ---------------- double-float (two-float) arithmetic -----------------
struct df { float h, l; };

__device__ __forceinline__ df qts(float a, float b) {          // |a| >= |b|
    float s = a + b;
    return { s, b - (s - a) };
}
__device__ __forceinline__ df two_sum(float a, float b) {
    float s = a + b;
    float t = s - a;
    return { s, (a - (s - t)) + (b - t) };
}
__device__ __forceinline__ df two_prod(float a, float b) {
    float p = a * b;
    return { p, fmaf(a, b, -p) };
}
__device__ __forceinline__ df df_mul(df a, df b) {
    df p = two_prod(a.h, b.h);
    p.l = p.l + (a.h * b.l + a.l * b.h);
    return qts(p.h, p.l);
}
__device__ __forceinline__ df df_mul_f(df a, float b) {
    df p = two_prod(a.h, b);
    p.l = p.l + a.l * b;
    return qts(p.h, p.l);
}
__device__ __forceinline__ df df_add(df a, df b) {
    df s = two_sum(a.h, b.h);
    s.l = s.l + (a.l + b.l);
    return qts(s.h, s.l);
}
// -----------------------------------------------------------------------

// Cephes/Eigen-style vectorized expf (what XLA:CPU / MLIR math-approx emits),
// fma form (pmadd is fused on NEON/AVX2).
__device__ float cephes_expf(float x) {
    const float LOG2EF = 1.44269504088896341f;
    const float C1 = 0.693359375f;
    const float C2 = -2.12194440e-4f;
    float m = floorf(fmaf(x, LOG2EF, 0.5f));
    float r = fmaf(m, -C1, x);
    r = fmaf(m, -C2, r);
    float r2 = __fmul_rn(r, r);
    float y = 1.9875691500E-4f;
    y = fmaf(y, r, 1.3981999507E-3f);
    y = fmaf(y, r, 8.3334519073E-3f);
    y = fmaf(y, r, 4.1665795894E-2f);
    y = fmaf(y, r, 1.6666665459E-1f);
    y = fmaf(y, r, 5.0000001201E-1f);
    y = fmaf(y, r2, r);
    y = __fadd_rn(y, 1.0f);
    return ldexpf(y, (int)m);
}

// fp32 Keys cubic weight with SEPARATE roundings per elementary op,
// matching eager XLA elementwise semantics (no FMA contraction).
__device__ float keys_f32_strict(float x) {
    // ((1.5*x - 2.5) * x) * x + 1
    float t1 = __fmul_rn(1.5f, x);
    float t2 = __fsub_rn(t1, 2.5f);
    float t3 = __fmul_rn(t2, x);
    float t4 = __fmul_rn(t3, x);
    float out = __fadd_rn(t4, 1.0f);
    if (x >= 1.0f) {
        // ((-0.5*x + 2.5) * x - 4) * x + 2
        float u1 = __fmul_rn(-0.5f, x);
        float u2 = __fadd_rn(u1, 2.5f);
        float u3 = __fmul_rn(u2, x);
        float u4 = __fsub_rn(u3, 4.0f);
        float u5 = __fmul_rn(u4, x);
        out = __fadd_rn(u5, 2.0f);
    }
    if (x >= 2.0f) out = 0.0f;
    return out;
}

__global__ void precompute_E_kernel() {
    int p = threadIdx.x;  // 0..127 output position
    if (p >= 128) return;

    // Gaussian taps mimicking eager jax fp32 on CPU: ax = arange(-7, 9)
    float kf[16];
    float ksum = 0.0f;
    #pragma unroll
    for (int j = 0; j < 16; ++j) {
        float off = (float)(j - 7);
        float sq = __fmul_rn(off, off);                 // exact
        float arg = -__fdiv_rn(sq, 12.5f);              // 2*sigma^2 = 12.5
        kf[j] = cephes_expf(arg);
        ksum = __fadd_rn(ksum, kf[j]);                  // sequential reduce
    }
    double taps[16];
    #pragma unroll
    for (int j = 0; j < 16; ++j)
        taps[j] = (double)__fdiv_rn(kf[j], ksum);       // fp32 divide, promote

    double E[4] = {0.0, 0.0, 0.0, 0.0};
    #pragma unroll
    for (int j = 0; j < 16; ++j) {
        int q = p - 7 + j;                              // conv offset, zero pad
        if (q < 0 || q >= 128) continue;
        // resize weights, strict fp32: sample_f = (q+0.5)*(1/32) - 0.5
        float sf = __fsub_rn(__fmul_rn(__fadd_rn((float)q, 0.5f), 0.03125f), 0.5f);
        float wc[4];
        float ssum = 0.0f;
        #pragma unroll
        for (int c = 0; c < 4; ++c) {
            float x = fabsf(__fsub_rn(sf, (float)c));
            wc[c] = keys_f32_strict(x);
            ssum = __fadd_rn(ssum, wc[c]);
        }
        #pragma unroll
        for (int c = 0; c < 4; ++c) {
            double w = (double)__fdiv_rn(wc[c], ssum);  // fp32 renorm, promote
            E[c] += taps[j] * w;                        // exact-ish fusion
        }
    }
    #pragma unroll
    for (int c = 0; c < 4; ++c) {
        float hi = (float)E[c];
        g_Ehi[p * 4 + c] = hi;
        g_Elo[p * 4 + c] = (float)(E[c] - (double)hi);
    }
}

__device__ __forceinline__ int clamp127(int v) {
    return min(max(v, 0), 127);
}

__global__ void __launch_bounds__(128) deform_kernel(
    const float* __restrict__ img,     // [B,128,128,128,4]
    const float* __restrict__ coarse,  // [B,4,4,4,3]
    const int*   __restrict__ lbl,     // [B,128,128,128]
    float*       __restrict__ out)     // [IMG_ELEMS] image then [VOX] label
{
    __shared__ float s_coarse[192];    // coarse[b] slice: 4*4*4*3
    __shared__ df    s_prod[16];       // E[d][cd]*E[h][ch]  (df)
    __shared__ df    s_U[12];          // U[cw][comp]        (df)

    int bid = blockIdx.x;
    int h = bid & 127;
    int d = (bid >> 7) & 127;
    int b = bid >> 14;
    int t = threadIdx.x;               // w coordinate

    for (int i = t; i < 192; i += 128) s_coarse[i] = coarse[b * 192 + i];
    if (t < 16) {
        int cd = t >> 2, ch = t & 3;
        df Ed = { g_Ehi[d * 4 + cd], g_Elo[d * 4 + cd] };
        df Eh = { g_Ehi[h * 4 + ch], g_Elo[h * 4 + ch] };
        s_prod[t] = df_mul(Ed, Eh);
    }
    __syncthreads();

    if (t < 12) {
        int cw = t / 3, comp = t - cw * 3;
        df acc = { 0.f, 0.f };
        #pragma unroll
        for (int k = 0; k < 16; ++k)
            acc = df_add(acc, df_mul_f(s_prod[k], s_coarse[(k * 4 + cw) * 3 + comp]));
        s_U[t] = acc;
    }
    __syncthreads();

    df Ew0 = { g_Ehi[t * 4 + 0], g_Elo[t * 4 + 0] };
    df Ew1 = { g_Ehi[t * 4 + 1], g_Elo[t * 4 + 1] };
    df Ew2 = { g_Ehi[t * 4 + 2], g_Elo[t * 4 + 2] };
    df Ew3 = { g_Ehi[t * 4 + 3], g_Elo[t * 4 + 3] };

    // flow (pre-scale) as near-exact df, then jax rounding chain:
    //   fl(flow) -> fl(35*flow) -> fl(grid + flow35)
    float flow[3];
    #pragma unroll
    for (int comp = 0; comp < 3; ++comp) {
        df acc =           df_mul(Ew0, s_U[0 * 3 + comp]);
        acc = df_add(acc,  df_mul(Ew1, s_U[1 * 3 + comp]));
        acc = df_add(acc,  df_mul(Ew2, s_U[2 * 3 + comp]));
        acc = df_add(acc,  df_mul(Ew3, s_U[3 * 3 + comp]));
        flow[comp] = acc.h + acc.l;    // round once to fp32
    }
    float wd = (float)d + 35.0f * flow[0];
    float wh = (float)h + 35.0f * flow[1];
    float ww = (float)t + 35.0f * flow[2];

    // trilinear sample of image (clamped corner indices, unclamped fractions)
    float fld = floorf(wd), flh = floorf(wh), flw = floorf(ww);
    float td = wd - fld, th = wh - flh, tw = ww - flw;
    int i0d = (int)fld, i0h = (int)flh, i0w = (int)flw;
    int d0 = clamp127(i0d),     h0 = clamp127(i0h),     w0 = clamp127(i0w);
    int d1 = clamp127(i0d + 1), h1 = clamp127(i0h + 1), w1 = clamp127(i0w + 1);

    const float4* __restrict__ img4 = reinterpret_cast<const float4*>(img);
    long base = (long)b * (128 * 128 * 128);
    #define AT(dz, hy, wx) img4[base + ((long)(dz) * 128 + (hy)) * 128 + (wx)]
    float4 c000 = AT(d0, h0, w0);
    float4 c001 = AT(d0, h0, w1);
    float4 c010 = AT(d0, h1, w0);
    float4 c011 = AT(d0, h1, w1);
    float4 c100 = AT(d1, h0, w0);
    float4 c101 = AT(d1, h0, w1);
    float4 c110 = AT(d1, h1, w0);
    float4 c111 = AT(d1, h1, w1);
    #undef AT

    float omw = 1.0f - tw, omh = 1.0f - th, omd = 1.0f - td;
    float4 r;
    {
        float c00, c01, c10, c11, c0, c1;
        c00 = c000.x * omw + c001.x * tw; c01 = c010.x * omw + c011.x * tw;
        c10 = c100.x * omw + c101.x * tw; c11 = c110.x * omw + c111.x * tw;
        c0 = c00 * omh + c01 * th; c1 = c10 * omh + c11 * th;
        r.x = c0 * omd + c1 * td;
        c00 = c000.y * omw + c001.y * tw; c01 = c010.y * omw + c011.y * tw;
        c10 = c100.y * omw + c101.y * tw; c11 = c110.y * omw + c111.y * tw;
        c0 = c00 * omh + c01 * th; c1 = c10 * omh + c11 * th;
        r.y = c0 * omd + c1 * td;
        c00 = c000.z * omw + c001.z * tw; c01 = c010.z * omw + c011.z * tw;
        c10 = c100.z * omw + c101.z * tw; c11 = c110.z * omw + c111.z * tw;
        c0 = c00 * omh + c01 * th; c1 = c10 * omh + c11 * th;
        r.z = c0 * omd + c1 * td;
        c00 = c000.w * omw + c001.w * tw; c01 = c010.w * omw + c011.w * tw;
        c10 = c100.w * omw + c101.w * tw; c11 = c110.w * omw + c111.w * tw;
        c0 = c00 * omh + c01 * th; c1 = c10 * omh + c11 * th;
        r.w = c0 * omd + c1 * td;
    }

    long ovox = base + ((long)d * 128 + h) * 128 + t;
    reinterpret_cast<float4*>(out)[ovox] = r;

    // nearest-neighbor label (jnp.round == round-half-even == rintf)
    int nd = clamp127((int)rintf(wd));
    int nh = clamp127((int)rintf(wh));
    int nw = clamp127((int)rintf(ww));
    int lv = lbl[base + ((long)nd * 128 + nh) * 128 + nw];
    out[IMG_ELEMS + ovox] = (float)lv;
}

extern "C" void kernel_launch(void* const* d_in, const int* in_sizes, int n_in,
                              void* d_out, int out_size) {
    const float* img = nullptr;
    const float* coarse = nullptr;
    const int*   lbl = nullptr;
    for (int i = 0; i < n_in; ++i) {
        if      (in_sizes[i] == IMG_ELEMS) img    = (const float*)d_in[i];
        else if (in_sizes[i] == 384)       coarse = (const float*)d_in[i];
        else if (in_sizes[i] == VOX)       lbl    = (const int*)d_in[i];
    }
    float* out = (float*)d_out;

    precompute_E_kernel<<<1, 128>>>();
    deform_kernel<<<BB * DD * HH, 128>>>(img, coarse, lbl, out);
}